// round 16
// baseline (speedup 1.0000x reference)
#include <cuda_runtime.h>

// TransD forward, simplified (eye is identity, RD==ED):
//   h_out = renorm(rp) * <renorm(hp), renorm(hv)> + renorm(hv)
//   rv_out = renorm(rv)
//   t_out = renorm(rp) * <renorm(tp), renorm(tv)> + renorm(tv)
//
// One warp -> 2 samples (s, s+NB/2), processed sequentially.
// At warp entry, fire-and-forget L2 bulk prefetches for sample 2's rows;
// sample 1's DRAM-latency gathers hide the prefetch flight time, so
// sample 2's gathers hit L2 (~240 cyc) instead of DRAM (~580 cyc).

#define NB 8192
#define DV 32u          // float4s per 128-float row
#define ROW_BYTES 512u
#define FULL 0xffffffffu

__device__ __forceinline__ float dot4(float4 a, float4 b) {
    return a.x * b.x + a.y * b.y + a.z * b.z + a.w * b.w;
}

__device__ __forceinline__ float rscale(float sumsq) {
    float n = sqrtf(sumsq);
    return (n > 1.0f) ? (1.0f / (n + 1e-7f)) : 1.0f;
}

__device__ __forceinline__ void st_cs(float4* p, float4 v) {
    asm volatile("st.global.cs.v4.f32 [%0], {%1,%2,%3,%4};"
                 :: "l"(p), "f"(v.x), "f"(v.y), "f"(v.z), "f"(v.w) : "memory");
}

__device__ __forceinline__ void l2_prefetch(const void* p) {
    asm volatile("cp.async.bulk.prefetch.L2.global [%0], %1;"
                 :: "l"(p), "r"(ROW_BYTES) : "memory");
}

// Process one sample: 6 gathers, 8-way reduction (R6 scheme), 3 row stores.
__device__ __forceinline__ void process_sample(
    const float4* __restrict__ ee, const float4* __restrict__ eep,
    const float4* __restrict__ re, const float4* __restrict__ rep,
    int hi, int ri, int ti, unsigned s, unsigned lane,
    float4* __restrict__ out)
{
    unsigned oh  = (unsigned)hi * DV + lane;
    unsigned ot  = (unsigned)ti * DV + lane;
    unsigned orr = (unsigned)ri * DV + lane;

    float4 hv = __ldg(ee  + oh);
    float4 hp = __ldg(eep + oh);
    float4 tv = __ldg(ee  + ot);
    float4 tp = __ldg(eep + ot);
    float4 rv = __ldg(re  + orr);
    float4 rp = __ldg(rep + orr);

    float p0 = dot4(hv, hv);
    float p1 = dot4(hp, hp);
    float p2 = dot4(tv, tv);
    float p3 = dot4(tp, tp);
    float p4 = dot4(rv, rv);
    float p5 = dot4(rp, rp);
    float p6 = dot4(hp, hv);
    float p7 = dot4(tp, tv);

    // stage A: each value reduced within groups of 4 lanes
    p0 += __shfl_xor_sync(FULL, p0, 1); p0 += __shfl_xor_sync(FULL, p0, 2);
    p1 += __shfl_xor_sync(FULL, p1, 1); p1 += __shfl_xor_sync(FULL, p1, 2);
    p2 += __shfl_xor_sync(FULL, p2, 1); p2 += __shfl_xor_sync(FULL, p2, 2);
    p3 += __shfl_xor_sync(FULL, p3, 1); p3 += __shfl_xor_sync(FULL, p3, 2);
    p4 += __shfl_xor_sync(FULL, p4, 1); p4 += __shfl_xor_sync(FULL, p4, 2);
    p5 += __shfl_xor_sync(FULL, p5, 1); p5 += __shfl_xor_sync(FULL, p5, 2);
    p6 += __shfl_xor_sync(FULL, p6, 1); p6 += __shfl_xor_sync(FULL, p6, 2);
    p7 += __shfl_xor_sync(FULL, p7, 1); p7 += __shfl_xor_sync(FULL, p7, 2);

    // stage B: lane (l&3) carries value q (w1) and 4+q (w2) through xor 4,8,16
    unsigned q = lane & 3u;
    float w1 = (q & 2u) ? ((q & 1u) ? p3 : p2) : ((q & 1u) ? p1 : p0);
    float w2 = (q & 2u) ? ((q & 1u) ? p7 : p6) : ((q & 1u) ? p5 : p4);
    w1 += __shfl_xor_sync(FULL, w1, 4);
    w2 += __shfl_xor_sync(FULL, w2, 4);
    w1 += __shfl_xor_sync(FULL, w1, 8);
    w2 += __shfl_xor_sync(FULL, w2, 8);
    w1 += __shfl_xor_sync(FULL, w1, 16);
    w2 += __shfl_xor_sync(FULL, w2, 16);

    // distributed rscale (2 MUFU chains/lane), then broadcast
    float r1 = rscale(w1);   // q: 0:c_hv 1:c_hp 2:c_tv 3:c_tp
    float r2 = rscale(w2);   // q: 0:c_rv 1:c_rp

    float c_hv = __shfl_sync(FULL, r1, 0);
    float c_hp = __shfl_sync(FULL, r1, 1);
    float c_tv = __shfl_sync(FULL, r1, 2);
    float c_tp = __shfl_sync(FULL, r1, 3);
    float c_rv = __shfl_sync(FULL, r2, 0);
    float c_rp = __shfl_sync(FULL, r2, 1);
    float d_h  = __shfl_sync(FULL, w2, 2);
    float d_t  = __shfl_sync(FULL, w2, 3);

    float a_h = c_rp * (d_h * c_hp * c_hv);
    float a_t = c_rp * (d_t * c_tp * c_tv);

    unsigned base = s * DV + lane;

    float4 o;
    o.x = rp.x * a_h + hv.x * c_hv;
    o.y = rp.y * a_h + hv.y * c_hv;
    o.z = rp.z * a_h + hv.z * c_hv;
    o.w = rp.w * a_h + hv.w * c_hv;
    st_cs(&out[base], o);

    o.x = rv.x * c_rv; o.y = rv.y * c_rv; o.z = rv.z * c_rv; o.w = rv.w * c_rv;
    st_cs(&out[NB * DV + base], o);

    o.x = rp.x * a_t + tv.x * c_tv;
    o.y = rp.y * a_t + tv.y * c_tv;
    o.z = rp.z * a_t + tv.z * c_tv;
    o.w = rp.w * a_t + tv.w * c_tv;
    st_cs(&out[2u * NB * DV + base], o);
}

__global__ __launch_bounds__(128) void transd_kernel(
    const float4* __restrict__ ee,   // entity_emb      [ENT*32]
    const float4* __restrict__ eep,  // entity_emb_p    [ENT*32]
    const float4* __restrict__ re,   // relation_emb    [REL*32]
    const float4* __restrict__ rep,  // relation_emb_p  [REL*32]
    const int* __restrict__ h,
    const int* __restrict__ r,
    const int* __restrict__ t,
    float4* __restrict__ out)        // [3 * NB * 32]
{
    int gwarp = (blockIdx.x * blockDim.x + threadIdx.x) >> 5;
    unsigned lane = threadIdx.x & 31u;
    if (gwarp >= NB / 2) return;

    unsigned s0 = (unsigned)gwarp;
    unsigned s1 = (unsigned)gwarp + NB / 2;

    int hi0 = __ldg(&h[s0]), ri0 = __ldg(&r[s0]), ti0 = __ldg(&t[s0]);
    int hi1 = __ldg(&h[s1]), ri1 = __ldg(&r[s1]), ti1 = __ldg(&t[s1]);

    // fire-and-forget L2 prefetch of sample 2's rows (lane 0 only)
    if (lane == 0) {
        l2_prefetch((const char*)ee  + (size_t)hi1 * ROW_BYTES);
        l2_prefetch((const char*)eep + (size_t)hi1 * ROW_BYTES);
        l2_prefetch((const char*)ee  + (size_t)ti1 * ROW_BYTES);
        l2_prefetch((const char*)eep + (size_t)ti1 * ROW_BYTES);
        l2_prefetch((const char*)re  + (size_t)ri1 * ROW_BYTES);
        l2_prefetch((const char*)rep + (size_t)ri1 * ROW_BYTES);
    }

    // sample 1: gathers take full DRAM latency, hiding prefetch flight
    process_sample(ee, eep, re, rep, hi0, ri0, ti0, s0, lane, out);
    // sample 2: gathers should now be L2 hits
    process_sample(ee, eep, re, rep, hi1, ri1, ti1, s1, lane, out);
}

extern "C" void kernel_launch(void* const* d_in, const int* in_sizes, int n_in,
                              void* d_out, int out_size) {
    const float4* ee  = (const float4*)d_in[0];
    const float4* eep = (const float4*)d_in[1];
    const float4* re  = (const float4*)d_in[2];
    const float4* rep = (const float4*)d_in[3];
    const int* h = (const int*)d_in[4];
    const int* r = (const int*)d_in[5];
    const int* t = (const int*)d_in[6];

    // 2 samples/warp -> 4096 warps -> 1024 blocks of 128 threads
    int blocks = (NB / 2 * 32 + 127) / 128;
    transd_kernel<<<blocks, 128>>>(ee, eep, re, rep, h, r, t, (float4*)d_out);
}